// round 2
// baseline (speedup 1.0000x reference)
#include <cuda_runtime.h>
#include <cuda_bf16.h>

#define L_SEQ   16384
#define D_MOD   1024
#define H_DIM   1024
#define T_CHUNK 128
#define N_CHUNK 128   // L_SEQ / T_CHUNK

// ---------------- static scratch (no allocations allowed) ----------------
__device__ float g_Bre_s[H_DIM * D_MOD];
__device__ float g_Bim_s[H_DIM * D_MOD];
__device__ float g_Bu_re[L_SEQ * H_DIM];
__device__ float g_Bu_im[L_SEQ * H_DIM];
__device__ float g_Hre[L_SEQ * H_DIM];
__device__ float g_Him[L_SEQ * H_DIM];
__device__ float g_lre[H_DIM], g_lim[H_DIM];
__device__ float g_lTre[H_DIM], g_lTim[H_DIM];
__device__ float g_Ere[N_CHUNK * H_DIM], g_Eim[N_CHUNK * H_DIM];
__device__ float g_Sre[N_CHUNK * H_DIM], g_Sim[N_CHUNK * H_DIM];

// ---------------- param prep ----------------
__global__ void prep_params(const float* __restrict__ nu_log,
                            const float* __restrict__ theta_log) {
    int h = blockIdx.x * blockDim.x + threadIdx.x;
    if (h >= H_DIM) return;
    float nu = expf(nu_log[h]);
    float th = expf(theta_log[h]);
    float mag = expf(-nu);
    float lre = mag * cosf(th);
    float lim = mag * sinf(th);
    g_lre[h] = lre; g_lim[h] = lim;
    // lambda^T_CHUNK by repeated multiply (matches scan arithmetic closely)
    float ar = 1.f, ai = 0.f;
    for (int t = 0; t < T_CHUNK; t++) {
        float nr = ar * lre - ai * lim;
        ai = ar * lim + ai * lre;
        ar = nr;
    }
    g_lTre[h] = ar; g_lTim[h] = ai;
}

__global__ void scale_B(const float* __restrict__ Bre,
                        const float* __restrict__ Bim,
                        const float* __restrict__ gamma_log) {
    int h = blockIdx.x;
    int d = blockIdx.y * blockDim.x + threadIdx.x;
    float eg = expf(gamma_log[h]);
    int idx = h * D_MOD + d;
    g_Bre_s[idx] = Bre[idx] * eg;
    g_Bim_s[idx] = Bim[idx] * eg;
}

// ---------------- GEMM1: dual-output NT gemm (shared A tile) ----------------
// O1[m,n] = sum_k A[m,k] W1[n,k];  O2 likewise with W2.  M%128==0, N%64==0, K%16==0
__global__ __launch_bounds__(256, 2) void gemm_ab2(
    const float* __restrict__ A, const float* __restrict__ W1,
    const float* __restrict__ W2, float* __restrict__ O1,
    float* __restrict__ O2, int M, int N, int K)
{
    __shared__ float As[16][128];
    __shared__ float W1s[16][64];
    __shared__ float W2s[16][64];
    const int tid = threadIdx.x;
    const int tx = tid & 15, ty = tid >> 4;
    const int m0 = blockIdx.x * 128, n0 = blockIdx.y * 64;

    const int arow = tid >> 2;      // 0..63
    const int ac4  = tid & 3;       // which float4 along K
    const float* pA0 = A  + (size_t)(m0 + arow) * K + ac4 * 4;
    const float* pA1 = pA0 + (size_t)64 * K;
    const float* pW1 = W1 + (size_t)(n0 + arow) * K + ac4 * 4;
    const float* pW2 = W2 + (size_t)(n0 + arow) * K + ac4 * 4;

    float4 ra0 = *(const float4*)pA0;
    float4 ra1 = *(const float4*)pA1;
    float4 rw1 = *(const float4*)pW1;
    float4 rw2 = *(const float4*)pW2;

    float acc1[8][4], acc2[8][4];
#pragma unroll
    for (int r = 0; r < 8; r++)
#pragma unroll
        for (int c = 0; c < 4; c++) { acc1[r][c] = 0.f; acc2[r][c] = 0.f; }

    for (int k0 = 0; k0 < K; k0 += 16) {
        __syncthreads();
        As[ac4*4+0][arow]    = ra0.x; As[ac4*4+1][arow]    = ra0.y;
        As[ac4*4+2][arow]    = ra0.z; As[ac4*4+3][arow]    = ra0.w;
        As[ac4*4+0][arow+64] = ra1.x; As[ac4*4+1][arow+64] = ra1.y;
        As[ac4*4+2][arow+64] = ra1.z; As[ac4*4+3][arow+64] = ra1.w;
        W1s[ac4*4+0][arow] = rw1.x; W1s[ac4*4+1][arow] = rw1.y;
        W1s[ac4*4+2][arow] = rw1.z; W1s[ac4*4+3][arow] = rw1.w;
        W2s[ac4*4+0][arow] = rw2.x; W2s[ac4*4+1][arow] = rw2.y;
        W2s[ac4*4+2][arow] = rw2.z; W2s[ac4*4+3][arow] = rw2.w;
        __syncthreads();
        if (k0 + 16 < K) {
            ra0 = *(const float4*)(pA0 + k0 + 16);
            ra1 = *(const float4*)(pA1 + k0 + 16);
            rw1 = *(const float4*)(pW1 + k0 + 16);
            rw2 = *(const float4*)(pW2 + k0 + 16);
        }
#pragma unroll
        for (int k = 0; k < 16; k++) {
            float4 a0 = *(const float4*)&As[k][ty * 8];
            float4 a1 = *(const float4*)&As[k][ty * 8 + 4];
            float4 w1 = *(const float4*)&W1s[k][tx * 4];
            float4 w2 = *(const float4*)&W2s[k][tx * 4];
            float av[8]  = {a0.x,a0.y,a0.z,a0.w,a1.x,a1.y,a1.z,a1.w};
            float w1v[4] = {w1.x,w1.y,w1.z,w1.w};
            float w2v[4] = {w2.x,w2.y,w2.z,w2.w};
#pragma unroll
            for (int r = 0; r < 8; r++)
#pragma unroll
                for (int c = 0; c < 4; c++) {
                    acc1[r][c] = fmaf(av[r], w1v[c], acc1[r][c]);
                    acc2[r][c] = fmaf(av[r], w2v[c], acc2[r][c]);
                }
        }
    }
#pragma unroll
    for (int r = 0; r < 8; r++) {
        size_t m = m0 + ty * 8 + r;
        float4 v1 = make_float4(acc1[r][0], acc1[r][1], acc1[r][2], acc1[r][3]);
        float4 v2 = make_float4(acc2[r][0], acc2[r][1], acc2[r][2], acc2[r][3]);
        *(float4*)(O1 + m * N + n0 + tx * 4) = v1;
        *(float4*)(O2 + m * N + n0 + tx * 4) = v2;
    }
}

// ---------------- GEMM2: O = A1 W1^T - A2 W2^T + Dp*X ----------------
__global__ __launch_bounds__(256, 2) void gemm_combine(
    const float* __restrict__ A1, const float* __restrict__ W1,
    const float* __restrict__ A2, const float* __restrict__ W2,
    const float* __restrict__ X, const float* __restrict__ Dp,
    float* __restrict__ O, int M, int N, int K)
{
    __shared__ float A1s[16][128];
    __shared__ float A2s[16][128];
    __shared__ float W1s[16][64];
    __shared__ float W2s[16][64];
    const int tid = threadIdx.x;
    const int tx = tid & 15, ty = tid >> 4;
    const int m0 = blockIdx.x * 128, n0 = blockIdx.y * 64;

    const int arow = tid >> 2;
    const int ac4  = tid & 3;
    const float* pA1a = A1 + (size_t)(m0 + arow) * K + ac4 * 4;
    const float* pA1b = pA1a + (size_t)64 * K;
    const float* pA2a = A2 + (size_t)(m0 + arow) * K + ac4 * 4;
    const float* pA2b = pA2a + (size_t)64 * K;
    const float* pW1 = W1 + (size_t)(n0 + arow) * K + ac4 * 4;
    const float* pW2 = W2 + (size_t)(n0 + arow) * K + ac4 * 4;

    float4 r1a = *(const float4*)pA1a;
    float4 r1b = *(const float4*)pA1b;
    float4 r2a = *(const float4*)pA2a;
    float4 r2b = *(const float4*)pA2b;
    float4 rw1 = *(const float4*)pW1;
    float4 rw2 = *(const float4*)pW2;

    float acc[8][4];
#pragma unroll
    for (int r = 0; r < 8; r++)
#pragma unroll
        for (int c = 0; c < 4; c++) acc[r][c] = 0.f;

    for (int k0 = 0; k0 < K; k0 += 16) {
        __syncthreads();
        A1s[ac4*4+0][arow]    = r1a.x; A1s[ac4*4+1][arow]    = r1a.y;
        A1s[ac4*4+2][arow]    = r1a.z; A1s[ac4*4+3][arow]    = r1a.w;
        A1s[ac4*4+0][arow+64] = r1b.x; A1s[ac4*4+1][arow+64] = r1b.y;
        A1s[ac4*4+2][arow+64] = r1b.z; A1s[ac4*4+3][arow+64] = r1b.w;
        A2s[ac4*4+0][arow]    = r2a.x; A2s[ac4*4+1][arow]    = r2a.y;
        A2s[ac4*4+2][arow]    = r2a.z; A2s[ac4*4+3][arow]    = r2a.w;
        A2s[ac4*4+0][arow+64] = r2b.x; A2s[ac4*4+1][arow+64] = r2b.y;
        A2s[ac4*4+2][arow+64] = r2b.z; A2s[ac4*4+3][arow+64] = r2b.w;
        W1s[ac4*4+0][arow] = rw1.x; W1s[ac4*4+1][arow] = rw1.y;
        W1s[ac4*4+2][arow] = rw1.z; W1s[ac4*4+3][arow] = rw1.w;
        W2s[ac4*4+0][arow] = rw2.x; W2s[ac4*4+1][arow] = rw2.y;
        W2s[ac4*4+2][arow] = rw2.z; W2s[ac4*4+3][arow] = rw2.w;
        __syncthreads();
        if (k0 + 16 < K) {
            r1a = *(const float4*)(pA1a + k0 + 16);
            r1b = *(const float4*)(pA1b + k0 + 16);
            r2a = *(const float4*)(pA2a + k0 + 16);
            r2b = *(const float4*)(pA2b + k0 + 16);
            rw1 = *(const float4*)(pW1 + k0 + 16);
            rw2 = *(const float4*)(pW2 + k0 + 16);
        }
#pragma unroll
        for (int k = 0; k < 16; k++) {
            float4 a0 = *(const float4*)&A1s[k][ty * 8];
            float4 a1 = *(const float4*)&A1s[k][ty * 8 + 4];
            float4 b0 = *(const float4*)&A2s[k][ty * 8];
            float4 b1 = *(const float4*)&A2s[k][ty * 8 + 4];
            float4 w1 = *(const float4*)&W1s[k][tx * 4];
            float4 w2 = *(const float4*)&W2s[k][tx * 4];
            float av[8] = {a0.x,a0.y,a0.z,a0.w,a1.x,a1.y,a1.z,a1.w};
            float bv[8] = {b0.x,b0.y,b0.z,b0.w,b1.x,b1.y,b1.z,b1.w};
            float w1v[4] = {w1.x,w1.y,w1.z,w1.w};
            float w2v[4] = {w2.x,w2.y,w2.z,w2.w};
#pragma unroll
            for (int r = 0; r < 8; r++)
#pragma unroll
                for (int c = 0; c < 4; c++) {
                    acc[r][c] = fmaf(av[r],  w1v[c], acc[r][c]);
                    acc[r][c] = fmaf(-bv[r], w2v[c], acc[r][c]);
                }
        }
    }
    float4 dp = *(const float4*)(Dp + n0 + tx * 4);
#pragma unroll
    for (int r = 0; r < 8; r++) {
        size_t m = m0 + ty * 8 + r;
        float4 xx = *(const float4*)(X + m * N + n0 + tx * 4);
        float4 v;
        v.x = acc[r][0] + dp.x * xx.x;
        v.y = acc[r][1] + dp.y * xx.y;
        v.z = acc[r][2] + dp.z * xx.z;
        v.w = acc[r][3] + dp.w * xx.w;
        *(float4*)(O + m * N + n0 + tx * 4) = v;
    }
}

// ---------------- scan pass A: per-chunk end states ----------------
__global__ void scan_chunks() {
    int h = blockIdx.x * blockDim.x + threadIdx.x;
    int c = blockIdx.y;
    float lre = g_lre[h], lim = g_lim[h];
    float hr = 0.f, hi = 0.f;
    size_t base = (size_t)c * T_CHUNK * H_DIM + h;
#pragma unroll 4
    for (int t = 0; t < T_CHUNK; t++) {
        float br = g_Bu_re[base + (size_t)t * H_DIM];
        float bi = g_Bu_im[base + (size_t)t * H_DIM];
        float nr = fmaf(lre, hr, fmaf(-lim, hi, br));
        float ni = fmaf(lre, hi, fmaf(lim, hr, bi));
        hr = nr; hi = ni;
    }
    g_Ere[c * H_DIM + h] = hr;
    g_Eim[c * H_DIM + h] = hi;
}

// ---------------- scan pass B: cross-chunk prefix + final state ----------------
// head_mode: 0 = no head write, 1 = real-part only (1024 floats),
//            2 = interleaved complex64-as-float32 (2048 floats)
__global__ void scan_combine(float* __restrict__ out_head, int head_mode) {
    int h = blockIdx.x * blockDim.x + threadIdx.x;
    float lTre = g_lTre[h], lTim = g_lTim[h];
    float sr = 0.f, si = 0.f;
    for (int c = 0; c < N_CHUNK; c++) {
        g_Sre[c * H_DIM + h] = sr;
        g_Sim[c * H_DIM + h] = si;
        float er = g_Ere[c * H_DIM + h];
        float ei = g_Eim[c * H_DIM + h];
        float nr = fmaf(lTre, sr, fmaf(-lTim, si, er));
        float ni = fmaf(lTre, si, fmaf(lTim, sr, ei));
        sr = nr; si = ni;
    }
    if (head_mode == 1) {
        out_head[h] = sr;            // complex->float32 astype drops imag
    } else if (head_mode == 2) {
        out_head[2 * h]     = sr;    // complex64 viewed as float pairs
        out_head[2 * h + 1] = si;
    }
}

// ---------------- scan pass C: apply with correct initial states ----------------
__global__ void scan_apply() {
    int h = blockIdx.x * blockDim.x + threadIdx.x;
    int c = blockIdx.y;
    float lre = g_lre[h], lim = g_lim[h];
    float hr = g_Sre[c * H_DIM + h];
    float hi = g_Sim[c * H_DIM + h];
    size_t base = (size_t)c * T_CHUNK * H_DIM + h;
#pragma unroll 4
    for (int t = 0; t < T_CHUNK; t++) {
        float br = g_Bu_re[base + (size_t)t * H_DIM];
        float bi = g_Bu_im[base + (size_t)t * H_DIM];
        float nr = fmaf(lre, hr, fmaf(-lim, hi, br));
        float ni = fmaf(lre, hi, fmaf(lim, hr, bi));
        hr = nr; hi = ni;
        g_Hre[base + (size_t)t * H_DIM] = hr;
        g_Him[base + (size_t)t * H_DIM] = hi;
    }
}

// ---------------- launch ----------------
extern "C" void kernel_launch(void* const* d_in, const int* in_sizes, int n_in,
                              void* d_out, int out_size) {
    const float* x         = (const float*)d_in[0];
    const float* nu_log    = (const float*)d_in[1];
    const float* theta_log = (const float*)d_in[2];
    const float* gamma_log = (const float*)d_in[3];
    const float* Bre       = (const float*)d_in[4];
    const float* Bim       = (const float*)d_in[5];
    const float* Cre       = (const float*)d_in[6];
    const float* Cim       = (const float*)d_in[7];
    const float* Dp        = (const float*)d_in[8];

    float* out = (float*)d_out;
    long long head = (long long)out_size - (long long)L_SEQ * D_MOD;
    if (head < 0) head = 0;
    int head_mode = 0;
    if (head >= 2 * H_DIM)      head_mode = 2;   // interleaved complex
    else if (head >= H_DIM)     head_mode = 1;   // real part only
    float* out_head = out;
    float* out_y = out + head;

    float *pBreS, *pBimS, *pBuRe, *pBuIm, *pHre, *pHim;
    cudaGetSymbolAddress((void**)&pBreS, g_Bre_s);
    cudaGetSymbolAddress((void**)&pBimS, g_Bim_s);
    cudaGetSymbolAddress((void**)&pBuRe, g_Bu_re);
    cudaGetSymbolAddress((void**)&pBuIm, g_Bu_im);
    cudaGetSymbolAddress((void**)&pHre,  g_Hre);
    cudaGetSymbolAddress((void**)&pHim,  g_Him);

    prep_params<<<H_DIM / 256, 256>>>(nu_log, theta_log);
    scale_B<<<dim3(H_DIM, D_MOD / 256), 256>>>(Bre, Bim, gamma_log);

    // Bu = x @ (B*e^gamma)^T   (re and im share the A tile)
    gemm_ab2<<<dim3(L_SEQ / 128, H_DIM / 64), 256>>>(
        x, pBreS, pBimS, pBuRe, pBuIm, L_SEQ, H_DIM, D_MOD);

    scan_chunks<<<dim3(H_DIM / 256, N_CHUNK), 256>>>();
    scan_combine<<<H_DIM / 256, 256>>>(out_head, head_mode);
    scan_apply<<<dim3(H_DIM / 256, N_CHUNK), 256>>>();

    // y = Hre @ Cre^T - Him @ Cim^T + Dp * x
    gemm_combine<<<dim3(L_SEQ / 128, D_MOD / 64), 256>>>(
        pHre, Cre, pHim, Cim, x, Dp, out_y, L_SEQ, D_MOD, H_DIM);
}

// round 5
// speedup vs baseline: 2.4483x; 2.4483x over previous
#include <cuda_runtime.h>
#include <cuda_bf16.h>
#include <cstdint>

#define L_SEQ   16384
#define D_MOD   1024
#define H_DIM   1024
#define T_CHUNK 128
#define N_CHUNK 128   // L_SEQ / T_CHUNK

// ---------------- static scratch ----------------
__device__ float g_xr [(size_t)L_SEQ * D_MOD];          // tf32-rounded x
__device__ float g_W1 [(size_t)2 * H_DIM * D_MOD];      // [2048 x 1024] stacked re/im of scaled B (tf32)
__device__ float g_W2 [(size_t)D_MOD * 2 * H_DIM];      // [1024 x 2048] = [Cre | -Cim] (tf32)
__device__ float g_Bu [(size_t)L_SEQ * 2 * H_DIM];      // [16384 x 2048] Bu, then H (tf32) in place
__device__ float g_lre[H_DIM], g_lim[H_DIM];
__device__ float g_lTre[H_DIM], g_lTim[H_DIM];
__device__ float g_Ere[N_CHUNK * H_DIM], g_Eim[N_CHUNK * H_DIM];
__device__ float g_Sre[N_CHUNK * H_DIM], g_Sim[N_CHUNK * H_DIM];

// ---------------- helpers ----------------
__device__ __forceinline__ float tf32r(float x) {     // round-to-nearest tf32
    uint32_t u;
    asm("cvt.rna.tf32.f32 %0, %1;" : "=r"(u) : "f"(x));
    return __uint_as_float(u);
}
__device__ __forceinline__ void cp16(uint32_t dst, const void* src) {
    asm volatile("cp.async.cg.shared.global [%0], [%1], 16;" :: "r"(dst), "l"(src) : "memory");
}
__device__ __forceinline__ void cp_commit() { asm volatile("cp.async.commit_group;" ::: "memory"); }
__device__ __forceinline__ void cp_wait1()  { asm volatile("cp.async.wait_group 1;" ::: "memory"); }
__device__ __forceinline__ void cp_wait0()  { asm volatile("cp.async.wait_group 0;" ::: "memory"); }
__device__ __forceinline__ uint32_t smem_u32(const void* p) {
    uint32_t a;
    asm("{ .reg .u64 t; cvta.to.shared.u64 t, %1; cvt.u32.u64 %0, t; }" : "=r"(a) : "l"(p));
    return a;
}
__device__ __forceinline__ void mma_tf32(float* c, uint32_t a0, uint32_t a1, uint32_t a2, uint32_t a3,
                                         uint32_t b0, uint32_t b1) {
    asm volatile(
        "mma.sync.aligned.m16n8k8.row.col.f32.tf32.tf32.f32 "
        "{%0,%1,%2,%3}, {%4,%5,%6,%7}, {%8,%9}, {%0,%1,%2,%3};\n"
        : "+f"(c[0]), "+f"(c[1]), "+f"(c[2]), "+f"(c[3])
        : "r"(a0), "r"(a1), "r"(a2), "r"(a3), "r"(b0), "r"(b1));
}

// smem tile geometry: 128 rows x 32 cols, row stride 36 floats (conflict-free: 36 ≡ 4 mod 32)
#define TSTRIDE   36
#define TILE_FLTS (128 * TSTRIDE)            // 4608 floats = 18432 B
#define STAGE_FLTS (2 * TILE_FLTS)           // A tile + B tile
#define SMEM_TOTAL (2 * STAGE_FLTS * 4)      // double buffered = 73728 B

// ---------------- TF32 NT GEMM: O[m,n] = sum_k A[m,k] * W[n,k]  (+ EPI: Dp[n]*X[m,n]) ----------------
template <int EPI>
__global__ __launch_bounds__(256, 2) void mma_gemm(
    const float* __restrict__ A, const float* __restrict__ W,
    float* __restrict__ O, int K, int Nout,
    const float* __restrict__ Dp, const float* __restrict__ X)
{
    extern __shared__ float smem[];
    const uint32_t sbase = smem_u32(smem);
    const int tid = threadIdx.x;
    const int wid = tid >> 5, lane = tid & 31;
    const int g = lane >> 2, tig = lane & 3;
    const int wm = wid & 3, wn = wid >> 2;           // 4 x 2 warps; warp tile 32 x 64
    const int m0 = blockIdx.x * 128, n0 = blockIdx.y * 128;
    const int NC = K >> 5;                           // K chunks of 32

    const int r_ld  = tid >> 1;                      // 0..127 (row loaded by this thread)
    const int c4_ld = (tid & 1) * 4;                 // float4 index pairs: covers c4 0..7 with i-loop

    auto load_chunk = [&](int stage, int kc) {
        const uint32_t sa = sbase + (uint32_t)(stage * STAGE_FLTS) * 4u;
        const uint32_t sb = sa + (uint32_t)TILE_FLTS * 4u;
        const int kbase = kc * 32;
#pragma unroll
        for (int i = 0; i < 4; i++) {                // 4 float4 per thread per tile
            int c4 = c4_ld + (i & 3);                // 0..7
            uint32_t doff = (uint32_t)(r_ld * TSTRIDE + c4 * 4) * 4u;
            cp16(sa + doff, A + (size_t)(m0 + r_ld) * K + kbase + c4 * 4);
            cp16(sb + doff, W + (size_t)(n0 + r_ld) * K + kbase + c4 * 4);
        }
    };

    float acc[2][8][4];
#pragma unroll
    for (int mt = 0; mt < 2; mt++)
#pragma unroll
        for (int nt = 0; nt < 8; nt++)
#pragma unroll
            for (int q = 0; q < 4; q++) acc[mt][nt][q] = 0.f;

    load_chunk(0, 0);
    cp_commit();

    for (int kc = 0; kc < NC; kc++) {
        if (kc + 1 < NC) {
            load_chunk((kc + 1) & 1, kc + 1);
            cp_commit();
            cp_wait1();
        } else {
            cp_wait0();
        }
        __syncthreads();
        const float* As = smem + (kc & 1) * STAGE_FLTS;
        const float* Bs = As + TILE_FLTS;
#pragma unroll
        for (int s = 0; s < 4; s++) {
            const int k0 = s * 8;
            uint32_t af[2][4];
#pragma unroll
            for (int mt = 0; mt < 2; mt++) {
                int r = wm * 32 + mt * 16 + g;
                af[mt][0] = __float_as_uint(As[r * TSTRIDE + k0 + tig]);
                af[mt][1] = __float_as_uint(As[(r + 8) * TSTRIDE + k0 + tig]);
                af[mt][2] = __float_as_uint(As[r * TSTRIDE + k0 + tig + 4]);
                af[mt][3] = __float_as_uint(As[(r + 8) * TSTRIDE + k0 + tig + 4]);
            }
            uint32_t bf[8][2];
#pragma unroll
            for (int nt = 0; nt < 8; nt++) {
                int n = wn * 64 + nt * 8 + g;
                bf[nt][0] = __float_as_uint(Bs[n * TSTRIDE + k0 + tig]);
                bf[nt][1] = __float_as_uint(Bs[n * TSTRIDE + k0 + tig + 4]);
            }
#pragma unroll
            for (int mt = 0; mt < 2; mt++)
#pragma unroll
                for (int nt = 0; nt < 8; nt++)
                    mma_tf32(acc[mt][nt], af[mt][0], af[mt][1], af[mt][2], af[mt][3],
                             bf[nt][0], bf[nt][1]);
        }
        __syncthreads();
    }

    // epilogue
#pragma unroll
    for (int mt = 0; mt < 2; mt++) {
        int row0 = m0 + wm * 32 + mt * 16 + g;
#pragma unroll
        for (int nt = 0; nt < 8; nt++) {
            int col = n0 + wn * 64 + nt * 8 + tig * 2;
            float2 v0 = make_float2(acc[mt][nt][0], acc[mt][nt][1]);
            float2 v1 = make_float2(acc[mt][nt][2], acc[mt][nt][3]);
            if (EPI) {
                float2 dp = *(const float2*)(Dp + col);
                float2 x0 = *(const float2*)(X + (size_t)row0 * 1024 + col);
                float2 x1 = *(const float2*)(X + (size_t)(row0 + 8) * 1024 + col);
                v0.x += dp.x * x0.x; v0.y += dp.y * x0.y;
                v1.x += dp.x * x1.x; v1.y += dp.y * x1.y;
            }
            *(float2*)(O + (size_t)row0 * Nout + col) = v0;
            *(float2*)(O + (size_t)(row0 + 8) * Nout + col) = v1;
        }
    }
}

// ---------------- conversions (tf32 pre-rounding) ----------------
__global__ void conv_x(const float* __restrict__ x) {
    size_t i = (size_t)(blockIdx.x * blockDim.x + threadIdx.x) * 4;
    float4 v = *(const float4*)(x + i);
    v.x = tf32r(v.x); v.y = tf32r(v.y); v.z = tf32r(v.z); v.w = tf32r(v.w);
    *(float4*)(g_xr + i) = v;
}

__global__ void prep_W1(const float* __restrict__ Bre, const float* __restrict__ Bim,
                        const float* __restrict__ gamma_log) {
    int n = blockIdx.x;             // 0..2047
    int h = n & 1023;
    const float* src = (n < 1024) ? Bre : Bim;
    float eg = expf(gamma_log[h]);
#pragma unroll
    for (int j = 0; j < 4; j++) {
        int k = threadIdx.x * 4 + j;
        g_W1[(size_t)n * 1024 + k] = tf32r(src[h * 1024 + k] * eg);
    }
}

__global__ void prep_W2(const float* __restrict__ Cre, const float* __restrict__ Cim) {
    int n = blockIdx.x;             // 0..1023
#pragma unroll
    for (int j = 0; j < 8; j++) {
        int k = threadIdx.x + j * 256;    // 0..2047
        float v = (k < 1024) ? Cre[n * 1024 + k] : -Cim[n * 1024 + (k - 1024)];
        g_W2[(size_t)n * 2048 + k] = tf32r(v);
    }
}

// ---------------- param prep ----------------
__global__ void prep_params(const float* __restrict__ nu_log,
                            const float* __restrict__ theta_log) {
    int h = blockIdx.x * blockDim.x + threadIdx.x;
    if (h >= H_DIM) return;
    float nu = expf(nu_log[h]);
    float th = expf(theta_log[h]);
    float mag = expf(-nu);
    float lre = mag * cosf(th);
    float lim = mag * sinf(th);
    g_lre[h] = lre; g_lim[h] = lim;
    float ar = 1.f, ai = 0.f;
    for (int t = 0; t < T_CHUNK; t++) {
        float nr = ar * lre - ai * lim;
        ai = ar * lim + ai * lre;
        ar = nr;
    }
    g_lTre[h] = ar; g_lTim[h] = ai;
}

// ---------------- scan (stacked [L x 2048]: re | im) ----------------
__global__ void scan_chunks() {
    int h = blockIdx.x * blockDim.x + threadIdx.x;
    int c = blockIdx.y;
    float lre = g_lre[h], lim = g_lim[h];
    float hr = 0.f, hi = 0.f;
#pragma unroll 4
    for (int t = 0; t < T_CHUNK; t++) {
        size_t row = (size_t)(c * T_CHUNK + t) * 2048;
        float br = g_Bu[row + h];
        float bi = g_Bu[row + 1024 + h];
        float nr = fmaf(lre, hr, fmaf(-lim, hi, br));
        float ni = fmaf(lre, hi, fmaf(lim, hr, bi));
        hr = nr; hi = ni;
    }
    g_Ere[c * H_DIM + h] = hr;
    g_Eim[c * H_DIM + h] = hi;
}

__global__ void scan_combine(float* __restrict__ out_head, int head_mode) {
    int h = blockIdx.x * blockDim.x + threadIdx.x;
    float lTre = g_lTre[h], lTim = g_lTim[h];
    float sr = 0.f, si = 0.f;
    for (int c = 0; c < N_CHUNK; c++) {
        g_Sre[c * H_DIM + h] = sr;
        g_Sim[c * H_DIM + h] = si;
        float er = g_Ere[c * H_DIM + h];
        float ei = g_Eim[c * H_DIM + h];
        float nr = fmaf(lTre, sr, fmaf(-lTim, si, er));
        float ni = fmaf(lTre, si, fmaf(lTim, sr, ei));
        sr = nr; si = ni;
    }
    if (head_mode == 1) {
        out_head[h] = sr;
    } else if (head_mode == 2) {
        out_head[2 * h]     = sr;
        out_head[2 * h + 1] = si;
    }
}

__global__ void scan_apply() {      // rewrites g_Bu in place with tf32-rounded hidden state
    int h = blockIdx.x * blockDim.x + threadIdx.x;
    int c = blockIdx.y;
    float lre = g_lre[h], lim = g_lim[h];
    float hr = g_Sre[c * H_DIM + h];
    float hi = g_Sim[c * H_DIM + h];
#pragma unroll 4
    for (int t = 0; t < T_CHUNK; t++) {
        size_t row = (size_t)(c * T_CHUNK + t) * 2048;
        float br = g_Bu[row + h];
        float bi = g_Bu[row + 1024 + h];
        float nr = fmaf(lre, hr, fmaf(-lim, hi, br));
        float ni = fmaf(lre, hi, fmaf(lim, hr, bi));
        hr = nr; hi = ni;
        g_Bu[row + h]        = tf32r(hr);
        g_Bu[row + 1024 + h] = tf32r(hi);
    }
}

// ---------------- launch ----------------
extern "C" void kernel_launch(void* const* d_in, const int* in_sizes, int n_in,
                              void* d_out, int out_size) {
    const float* x         = (const float*)d_in[0];
    const float* nu_log    = (const float*)d_in[1];
    const float* theta_log = (const float*)d_in[2];
    const float* gamma_log = (const float*)d_in[3];
    const float* Bre       = (const float*)d_in[4];
    const float* Bim       = (const float*)d_in[5];
    const float* Cre       = (const float*)d_in[6];
    const float* Cim       = (const float*)d_in[7];
    const float* Dp        = (const float*)d_in[8];

    float* out = (float*)d_out;
    long long head = (long long)out_size - (long long)L_SEQ * D_MOD;
    if (head < 0) head = 0;
    int head_mode = 0;
    if (head >= 2 * H_DIM)  head_mode = 2;
    else if (head >= H_DIM) head_mode = 1;
    float* out_head = out;
    float* out_y = out + head;

    float *pxr, *pW1, *pW2, *pBu;
    cudaGetSymbolAddress((void**)&pxr, g_xr);
    cudaGetSymbolAddress((void**)&pW1, g_W1);
    cudaGetSymbolAddress((void**)&pW2, g_W2);
    cudaGetSymbolAddress((void**)&pBu, g_Bu);

    cudaFuncSetAttribute(mma_gemm<0>, cudaFuncAttributeMaxDynamicSharedMemorySize, SMEM_TOTAL);
    cudaFuncSetAttribute(mma_gemm<1>, cudaFuncAttributeMaxDynamicSharedMemorySize, SMEM_TOTAL);

    prep_params<<<H_DIM / 256, 256>>>(nu_log, theta_log);
    conv_x<<<(L_SEQ * D_MOD) / (256 * 4), 256>>>(x);
    prep_W1<<<2 * H_DIM, 256>>>(Bre, Bim, gamma_log);
    prep_W2<<<D_MOD, 256>>>(Cre, Cim);

    // GEMM1: Bu[16384 x 2048] = x @ [B'_re ; B'_im]^T   (K=1024)
    mma_gemm<0><<<dim3(L_SEQ / 128, 2048 / 128), 256, SMEM_TOTAL>>>(
        pxr, pW1, pBu, 1024, 2048, nullptr, nullptr);

    scan_chunks<<<dim3(H_DIM / 256, N_CHUNK), 256>>>();
    scan_combine<<<H_DIM / 256, 256>>>(out_head, head_mode);
    scan_apply<<<dim3(H_DIM / 256, N_CHUNK), 256>>>();

    // GEMM2: y = [Hre|Him] @ [Cre|-Cim]^T + Dp*x   (K=2048)
    mma_gemm<1><<<dim3(L_SEQ / 128, 1024 / 128), 256, SMEM_TOTAL>>>(
        pBu, pW2, out_y, 2048, 1024, Dp, x);
}